// round 8
// baseline (speedup 1.0000x reference)
#include <cuda_runtime.h>
#include <cuda_fp16.h>
#include <cstdint>

#define BB 8192
#define DD 256
#define TM 128
#define TN 128
#define NSPLIT 2
#define CPS (BB/NSPLIT)     // 4096 cols per split
#define TT (CPS/TN)         // 32 tiles

static __device__ __align__(16) signed char g_a8[BB*DD];
static __device__ __align__(16) signed char g_p8[BB*DD];
static __device__ float g_fa[BB];     // per-row dequant factor (anchor)
static __device__ float g_fp[BB];     // per-row dequant factor (positive)
static __device__ float g_psum[NSPLIT][BB];
static __device__ float g_pmax[NSPLIT][BB];
static __device__ float g_diag[BB];

// dynamic smem: A 32KB, P0 32KB, P1 32KB, col-factor bufs 2x512B, stats 6KB
#define SM_A   0u
#define SM_P0  32768u
#define SM_P1  65536u
#define SM_FP0 98304u
#define SM_FP1 98816u
#define SM_ST  99328u
#define SMEM_BYTES (99328 + 6144)

#define INVT (1.0f/0.07f)
// exp((v-1)/T) = 2^(v*C1 - C1),  C1 = (1/T)*log2(e)
#define C1F 20.609929155556627f

__device__ __forceinline__ uint32_t s2u(const void* p) {
    uint32_t r;
    asm("{ .reg .u64 t; cvta.to.shared.u64 t, %1; cvt.u32.u64 %0, t; }" : "=r"(r) : "l"(p));
    return r;
}

// Load a 128x256 int8 tile (32KB) with 512 threads: each thread 4 chunks of 16B.
// Row stride 256B = 16 chunks; chunk' = chunk ^ (row & 7) xor swizzle.
__device__ __forceinline__ void load_tile8(uint32_t s_dst, const signed char* gtile, int tid) {
    const int row = tid >> 2;          // 0..127
    const int q   = tid & 3;
    const char* src = (const char*)gtile + (size_t)row * 256 + q * 64;
    const uint32_t rbase = s_dst + (uint32_t)row * 256u;
    const uint32_t rx = (uint32_t)(row & 7);
    #pragma unroll
    for (int j = 0; j < 4; ++j) {
        uint32_t chunk = (uint32_t)(q * 4 + j);
        uint32_t d = rbase + ((chunk ^ rx) << 4);
        asm volatile("cp.async.cg.shared.global [%0], [%1], 16;"
                     :: "r"(d), "l"(src + j * 16));
    }
}

#define LDSM_X4(r0, r1, r2, r3, addr) \
    asm volatile("ldmatrix.sync.aligned.m8n8.x4.shared.b16 {%0,%1,%2,%3}, [%4];" \
                 : "=r"(r0), "=r"(r1), "=r"(r2), "=r"(r3) : "r"(addr))

#define MMA16832I(c, a, b0v, b1v) \
    asm volatile("mma.sync.aligned.m16n8k32.row.col.s32.s8.s8.s32 " \
                 "{%0,%1,%2,%3}, {%4,%5,%6,%7}, {%8,%9}, {%0,%1,%2,%3};" \
                 : "+r"((c)[0]), "+r"((c)[1]), "+r"((c)[2]), "+r"((c)[3]) \
                 : "r"((a)[0]), "r"((a)[1]), "r"((a)[2]), "r"((a)[3]), \
                   "r"(b0v), "r"(b1v))

// Warp-per-row: L2-normalize fp32 row -> per-row-scaled int8 + dequant factor.
__global__ void nrmq_kernel(const float* __restrict__ a, const float* __restrict__ p) {
    int lane = threadIdx.x & 31;
    int row = blockIdx.x * 16 + (threadIdx.x >> 5);
    const float* src = (blockIdx.y ? p : a) + (size_t)row * DD + lane * 8;
    float v[8];
    *(float4*)&v[0] = *(const float4*)src;
    *(float4*)&v[4] = *(const float4*)(src + 4);
    float ss = 0.f, mv = 0.f;
    #pragma unroll
    for (int i = 0; i < 8; ++i) { ss += v[i]*v[i]; mv = fmaxf(mv, fabsf(v[i])); }
    #pragma unroll
    for (int o = 16; o > 0; o >>= 1) {
        ss += __shfl_xor_sync(0xffffffffu, ss, o);
        mv = fmaxf(mv, __shfl_xor_sync(0xffffffffu, mv, o));
    }
    float sc = 1.0f / fmaxf(sqrtf(ss), 1e-12f);
    float mvn = fmaxf(mv * sc, 1e-30f);       // max |normalized value| in row
    float qs = (127.0f / mvn) * sc;           // q = round(x * qs)
    int q[8];
    #pragma unroll
    for (int i = 0; i < 8; ++i) q[i] = __float2int_rn(v[i] * qs);
    uint32_t w0 = (uint32_t)(q[0] & 0xff) | ((uint32_t)(q[1] & 0xff) << 8)
                | ((uint32_t)(q[2] & 0xff) << 16) | ((uint32_t)(q[3] & 0xff) << 24);
    uint32_t w1 = (uint32_t)(q[4] & 0xff) | ((uint32_t)(q[5] & 0xff) << 8)
                | ((uint32_t)(q[6] & 0xff) << 16) | ((uint32_t)(q[7] & 0xff) << 24);
    signed char* dst = (blockIdx.y ? g_p8 : g_a8) + (size_t)row * DD + lane * 8;
    uint2 w; w.x = w0; w.y = w1;
    *(uint2*)dst = w;
    if (lane == 0) (blockIdx.y ? g_fp : g_fa)[row] = mvn * (1.0f / 127.0f);
}

__global__ __launch_bounds__(512, 1) void fused_kernel() {
    extern __shared__ char smem[];
    const uint32_t sb = s2u(smem);
    const int tid = threadIdx.x;
    const int lane = tid & 31, wid = tid >> 5;
    const int warp_m = wid >> 2;          // 0..3
    const int warp_n = wid & 3;           // 0..3
    const int bx = blockIdx.x, s = blockIdx.y;
    const int R0 = bx * TM;
    const int CB = s * CPS;
    // the single tile (if any) containing diagonal entries for this CTA
    const int t_diag = ((bx >> 5) == s) ? (bx & 31) : -1;

    // Prologue: A resident + P tiles 0,1 (+ per-column dequant factors)
    load_tile8(sb + SM_A,  g_a8 + (size_t)R0 * DD, tid);
    load_tile8(sb + SM_P0, g_p8 + (size_t)CB * DD, tid);
    if (tid < 32)
        asm volatile("cp.async.cg.shared.global [%0], [%1], 16;"
                     :: "r"(sb + SM_FP0 + (uint32_t)tid*16u),
                        "l"((const char*)(g_fp + CB) + tid*16));
    asm volatile("cp.async.commit_group;");
    load_tile8(sb + SM_P1, g_p8 + (size_t)(CB + TN) * DD, tid);
    if (tid < 32)
        asm volatile("cp.async.cg.shared.global [%0], [%1], 16;"
                     :: "r"(sb + SM_FP1 + (uint32_t)tid*16u),
                        "l"((const char*)(g_fp + CB + TN) + tid*16));
    asm volatile("cp.async.commit_group;");

    const uint32_t lrow  = (uint32_t)(lane & 15);
    const uint32_t khalf = (uint32_t)(lane >> 4);
    const uint32_t xorp  = (uint32_t)(lane & 7);

    uint32_t aBase[2];
    #pragma unroll
    for (int mf = 0; mf < 2; ++mf)
        aBase[mf] = sb + SM_A + (uint32_t)(warp_m*32 + mf*16 + (int)lrow) * 256u;

    const float NEGINF = __int_as_float(0xff800000);
    float sum[2][2], mx[2][2], dg[2][2];
    #pragma unroll
    for (int mf = 0; mf < 2; ++mf)
        #pragma unroll
        for (int h = 0; h < 2; ++h) { sum[mf][h]=0.f; mx[mf][h]=NEGINF; dg[mf][h]=0.f; }

    int grow[2][2];
    float fav[2][2];
    #pragma unroll
    for (int mf = 0; mf < 2; ++mf)
        #pragma unroll
        for (int h = 0; h < 2; ++h) {
            grow[mf][h] = R0 + warp_m*32 + mf*16 + (lane >> 2) + 8*h;
            fav[mf][h] = g_fa[grow[mf][h]];
        }

    #pragma unroll 1
    for (int t = 0; t < TT; ++t) {
        if (t + 1 < TT) asm volatile("cp.async.wait_group 1;");
        else            asm volatile("cp.async.wait_group 0;");
        __syncthreads();

        const uint32_t pb = (t & 1) ? SM_P1 : SM_P0;
        uint32_t bBase[2];
        #pragma unroll
        for (int nfp = 0; nfp < 2; ++nfp)
            bBase[nfp] = sb + pb + (uint32_t)(warp_n*32 + nfp*16 + (int)lrow) * 256u;

        int acc[2][4][4];
        #pragma unroll
        for (int mf = 0; mf < 2; ++mf)
            #pragma unroll
            for (int nf = 0; nf < 4; ++nf)
                #pragma unroll
                for (int e = 0; e < 4; ++e) acc[mf][nf][e] = 0;

        #pragma unroll
        for (int ks = 0; ks < 8; ++ks) {
            const uint32_t coff = (((uint32_t)(2*ks) + khalf) ^ xorp) << 4;
            uint32_t a[2][4];
            #pragma unroll
            for (int mf = 0; mf < 2; ++mf)
                LDSM_X4(a[mf][0], a[mf][1], a[mf][2], a[mf][3], aBase[mf] + coff);
            uint32_t b[2][4];
            #pragma unroll
            for (int nfp = 0; nfp < 2; ++nfp)
                LDSM_X4(b[nfp][0], b[nfp][1], b[nfp][2], b[nfp][3], bBase[nfp] + coff);
            #pragma unroll
            for (int mf = 0; mf < 2; ++mf) {
                MMA16832I(acc[mf][0], a[mf], b[0][0], b[0][2]);
                MMA16832I(acc[mf][1], a[mf], b[0][1], b[0][3]);
                MMA16832I(acc[mf][2], a[mf], b[1][0], b[1][2]);
                MMA16832I(acc[mf][3], a[mf], b[1][1], b[1][3]);
            }
        }

        // per-column dequant factors for this tile (read BEFORE the refill overwrites nothing:
        // factor buffers are double-buffered together with the tiles)
        const float* fpv = (const float*)(smem + ((t & 1) ? SM_FP1 : SM_FP0));
        const int cl0 = warp_n*32 + (lane & 3)*2;
        float2 f2[4];
        #pragma unroll
        for (int nf = 0; nf < 4; ++nf)
            f2[nf] = *(const float2*)&fpv[cl0 + nf*8];

        __syncthreads();
        if (t + 2 < TT) {
            load_tile8(sb + pb, g_p8 + (size_t)(CB + (t + 2) * TN) * DD, tid);
            if (tid < 32)
                asm volatile("cp.async.cg.shared.global [%0], [%1], 16;"
                             :: "r"(sb + ((t & 1) ? SM_FP1 : SM_FP0) + (uint32_t)tid*16u),
                                "l"((const char*)(g_fp + CB + (t + 2) * TN) + tid*16));
            asm volatile("cp.async.commit_group;");
        }

        // Epilogue: dequant + fold 128x128 tile into streaming stats
        if (t != t_diag) {
            #pragma unroll
            for (int mf = 0; mf < 2; ++mf) {
                #pragma unroll
                for (int h = 0; h < 2; ++h) {
                    const float fa = fav[mf][h];
                    float lsum = 0.f, lmx = mx[mf][h];
                    #pragma unroll
                    for (int nf = 0; nf < 4; ++nf) {
                        float v0 = (float)acc[mf][nf][h*2    ] * (fa * f2[nf].x);
                        float v1 = (float)acc[mf][nf][h*2 + 1] * (fa * f2[nf].y);
                        float ex0, ex1;
                        asm("ex2.approx.f32 %0, %1;" : "=f"(ex0) : "f"(fmaf(v0, C1F, -C1F)));
                        asm("ex2.approx.f32 %0, %1;" : "=f"(ex1) : "f"(fmaf(v1, C1F, -C1F)));
                        lsum += ex0 + ex1;
                        lmx = fmaxf(lmx, fmaxf(v0, v1));
                    }
                    sum[mf][h] += lsum;
                    mx[mf][h] = lmx;
                }
            }
        } else {
            const int cb0 = CB + t*TN + cl0;
            #pragma unroll
            for (int mf = 0; mf < 2; ++mf) {
                #pragma unroll
                for (int h = 0; h < 2; ++h) {
                    const float fa = fav[mf][h];
                    const int r = grow[mf][h];
                    float lsum = 0.f;
                    #pragma unroll
                    for (int nf = 0; nf < 4; ++nf) {
                        float v0 = (float)acc[mf][nf][h*2    ] * (fa * f2[nf].x);
                        float v1 = (float)acc[mf][nf][h*2 + 1] * (fa * f2[nf].y);
                        float ex0, ex1;
                        asm("ex2.approx.f32 %0, %1;" : "=f"(ex0) : "f"(fmaf(v0, C1F, -C1F)));
                        asm("ex2.approx.f32 %0, %1;" : "=f"(ex1) : "f"(fmaf(v1, C1F, -C1F)));
                        lsum += ex0 + ex1;
                        bool d0 = ((cb0 + nf*8    ) == r);
                        bool d1 = ((cb0 + nf*8 + 1) == r);
                        mx[mf][h] = fmaxf(mx[mf][h], d0 ? NEGINF : v0);
                        mx[mf][h] = fmaxf(mx[mf][h], d1 ? NEGINF : v1);
                        if (d0) dg[mf][h] = v0;
                        if (d1) dg[mf][h] = v1;
                    }
                    sum[mf][h] += lsum;
                }
            }
        }
    }

    // Quad reduction (lanes 4q..4q+3 share rows)
    #pragma unroll
    for (int mf = 0; mf < 2; ++mf) {
        #pragma unroll
        for (int h = 0; h < 2; ++h) {
            #pragma unroll
            for (int o = 1; o < 4; o <<= 1) {
                sum[mf][h] += __shfl_xor_sync(0xffffffffu, sum[mf][h], o);
                mx[mf][h]  = fmaxf(mx[mf][h], __shfl_xor_sync(0xffffffffu, mx[mf][h], o));
                dg[mf][h]  += __shfl_xor_sync(0xffffffffu, dg[mf][h], o);
            }
        }
    }

    // Cross-warp_n combine via smem stats region
    float* sSum = (float*)(smem + SM_ST);        // [4][128]
    float* sMax = sSum + 512;
    float* sDg  = sMax + 512;
    if ((lane & 3) == 0) {
        #pragma unroll
        for (int mf = 0; mf < 2; ++mf) {
            #pragma unroll
            for (int h = 0; h < 2; ++h) {
                int rl = warp_m*32 + mf*16 + (lane >> 2) + 8*h;
                sSum[warp_n*128 + rl] = sum[mf][h];
                sMax[warp_n*128 + rl] = mx[mf][h];
                sDg [warp_n*128 + rl] = dg[mf][h];
            }
        }
    }
    __syncthreads();
    if (tid < 128) {
        float S = 0.f, M = NEGINF, D = 0.f;
        #pragma unroll
        for (int w = 0; w < 4; ++w) {
            S += sSum[w*128 + tid];
            M = fmaxf(M, sMax[w*128 + tid]);
            D += sDg[w*128 + tid];
        }
        g_psum[s][R0 + tid] = S;
        g_pmax[s][R0 + tid] = M;
        if (t_diag >= 0) g_diag[R0 + tid] = D;
    }
}

__global__ void finalize_kernel(float* out) {
    __shared__ double sm[256];
    double sloc = 0.0;
    for (int i = threadIdx.x; i < BB; i += 256) {
        float sum = g_psum[0][i] + g_psum[1][i];
        float m = fmaxf(g_pmax[0][i], g_pmax[1][i]);
        float total = sum + __expf((m - 1.0f) * INVT);
        sloc += (double)(INVT * (1.0f - g_diag[i]) + logf(total));
    }
    sm[threadIdx.x] = sloc;
    __syncthreads();
    for (int st = 128; st > 0; st >>= 1) {
        if (threadIdx.x < st) sm[threadIdx.x] += sm[threadIdx.x + st];
        __syncthreads();
    }
    if (threadIdx.x == 0) out[0] = (float)(sm[0] / (double)BB);
}

extern "C" void kernel_launch(void* const* d_in, const int* in_sizes, int n_in,
                              void* d_out, int out_size) {
    const float* anchor   = (const float*)d_in[0];
    const float* positive = (const float*)d_in[1];
    cudaFuncSetAttribute(fused_kernel, cudaFuncAttributeMaxDynamicSharedMemorySize, SMEM_BYTES);
    nrmq_kernel<<<dim3(BB/16, 2), 512>>>(anchor, positive);
    fused_kernel<<<dim3(BB/TM, NSPLIT), 512, SMEM_BYTES>>>();
    finalize_kernel<<<1, 256>>>((float*)d_out);
}

// round 9
// speedup vs baseline: 1.9098x; 1.9098x over previous
#include <cuda_runtime.h>
#include <cuda_fp16.h>
#include <cstdint>

#define BB 8192
#define DD 256
#define TM 128
#define TN 128
#define NRB (BB/TM)          // 64 rowblocks
#define NCT (BB/TN)          // 64 col tiles
#define TOTW (NRB*NCT)       // 4096 tile visits
#define NCTA 148
#define WBASE (TOTW/NCTA)    // 27
#define WREM  (TOTW%NCTA)    // 100

static __device__ __align__(16) __half g_a16[BB*DD];
static __device__ __align__(16) __half g_p16[BB*DD];
static __device__ float    g_psum[BB];
static __device__ uint32_t g_pmaxu[BB];   // monotonic-mapped float
static __device__ float    g_diag[BB];

// dynamic smem: A @0 (64KB), P0 @64KB, P1 @128KB, stats @192KB
#define SM_A  0u
#define SM_P0 65536u
#define SM_P1 131072u
#define SM_ST 196608u
#define SMEM_BYTES (196608 + 6144)

#define INVT (1.0f/0.07f)
// exp((v-1)/T) = 2^(v*C1 - C1),  C1 = (1/T)*log2(e)
#define C1F 20.609929155556627f

__device__ __forceinline__ uint32_t s2u(const void* p) {
    uint32_t r;
    asm("{ .reg .u64 t; cvta.to.shared.u64 t, %1; cvt.u32.u64 %0, t; }" : "=r"(r) : "l"(p));
    return r;
}

// monotonic float<->uint mapping (order-preserving incl. negatives)
__device__ __forceinline__ uint32_t fmap(float x) {
    uint32_t u = __float_as_uint(x);
    return (u & 0x80000000u) ? ~u : (u | 0x80000000u);
}
__device__ __forceinline__ float funmap(uint32_t m) {
    uint32_t u = (m & 0x80000000u) ? (m & 0x7FFFFFFFu) : ~m;
    return __uint_as_float(u);
}

// Load a 128x256 fp16 tile (64KB) with 512 threads: each thread one row-quarter
// (8 chunks of 16B). Row stride 512B; chunk' = chunk ^ (row & 7) xor swizzle.
__device__ __forceinline__ void load_tile(uint32_t s_dst, const __half* gtile, int tid) {
    const int row = tid >> 2;          // 0..127
    const int q   = tid & 3;
    const char* src = (const char*)(gtile + (size_t)row * DD) + q * 128;
    const uint32_t rbase = s_dst + (uint32_t)row * 512u;
    const uint32_t rx = (uint32_t)(row & 7);
    #pragma unroll
    for (int j = 0; j < 8; ++j) {
        uint32_t chunk = (uint32_t)(q * 8 + j);
        uint32_t d = rbase + ((chunk ^ rx) << 4);
        asm volatile("cp.async.cg.shared.global [%0], [%1], 16;"
                     :: "r"(d), "l"(src + j * 16));
    }
}

#define LDSM_X4(r0, r1, r2, r3, addr) \
    asm volatile("ldmatrix.sync.aligned.m8n8.x4.shared.b16 {%0,%1,%2,%3}, [%4];" \
                 : "=r"(r0), "=r"(r1), "=r"(r2), "=r"(r3) : "r"(addr))

// fp16-accumulator MMA: acc = 2 b32 regs (4 half values)
#define MMA16816H(c, a, b0v, b1v) \
    asm volatile("mma.sync.aligned.m16n8k16.row.col.f16.f16.f16.f16 " \
                 "{%0,%1}, {%2,%3,%4,%5}, {%6,%7}, {%0,%1};" \
                 : "+r"((c)[0]), "+r"((c)[1]) \
                 : "r"((a)[0]), "r"((a)[1]), "r"((a)[2]), "r"((a)[3]), \
                   "r"(b0v), "r"(b1v))

// Warp-per-row: L2-normalize fp32 row -> fp16 row. Also resets per-row stats.
__global__ void nrm_kernel(const float* __restrict__ a, const float* __restrict__ p) {
    int lane = threadIdx.x & 31;
    int row = blockIdx.x * 16 + (threadIdx.x >> 5);
    if (blockIdx.y == 0 && lane == 0) {
        g_psum[row] = 0.f;
        g_pmaxu[row] = 0x007FFFFFu;   // fmap(-inf)
    }
    const float* src = (blockIdx.y ? p : a) + (size_t)row * DD + lane * 8;
    float4 v0 = *(const float4*)src;
    float4 v1 = *(const float4*)(src + 4);
    float ss = v0.x*v0.x + v0.y*v0.y + v0.z*v0.z + v0.w*v0.w
             + v1.x*v1.x + v1.y*v1.y + v1.z*v1.z + v1.w*v1.w;
    #pragma unroll
    for (int o = 16; o > 0; o >>= 1) ss += __shfl_xor_sync(0xffffffffu, ss, o);
    float sc = 1.0f / fmaxf(sqrtf(ss), 1e-12f);
    __half2 h[4];
    h[0] = __floats2half2_rn(v0.x*sc, v0.y*sc);
    h[1] = __floats2half2_rn(v0.z*sc, v0.w*sc);
    h[2] = __floats2half2_rn(v1.x*sc, v1.y*sc);
    h[3] = __floats2half2_rn(v1.z*sc, v1.w*sc);
    __half* dst = (blockIdx.y ? g_p16 : g_a16) + (size_t)row * DD + lane * 8;
    *(uint4*)dst = *(const uint4*)h;
}

__global__ __launch_bounds__(512, 1) void fused_kernel() {
    extern __shared__ char smem[];
    const uint32_t sb = s2u(smem);
    const int tid = threadIdx.x;
    const int lane = tid & 31, wid = tid >> 5;
    const int warp_m = wid >> 2;          // 0..3
    const int warp_n = wid & 3;           // 0..3
    const int c = blockIdx.x;

    // balanced contiguous range of tile visits
    const int start = WBASE * c + (c < WREM ? c : WREM);
    const int len   = WBASE + (c < WREM ? 1 : 0);
    const int rb0   = start >> 6;
    const int ct00  = start & 63;
    const int seg1  = (len < 64 - ct00) ? len : (64 - ct00);
    const int seg2  = len - seg1;

    const uint32_t lrow  = (uint32_t)(lane & 15);
    const uint32_t khalf = (uint32_t)(lane >> 4);
    const uint32_t xorp  = (uint32_t)(lane & 7);
    const float NEGINF = __int_as_float(0xff800000);

    uint32_t aBase[2];
    #pragma unroll
    for (int mf = 0; mf < 2; ++mf)
        aBase[mf] = sb + SM_A + (uint32_t)(warp_m*32 + mf*16 + (int)lrow) * 512u;

    float* sSum = (float*)(smem + SM_ST);        // [4][128]
    float* sMax = sSum + 512;
    float* sDg  = sMax + 512;

    #pragma unroll 1
    for (int sg = 0; sg < 2; ++sg) {
        int rb, cbeg, cend;
        if (sg == 0) { rb = rb0; cbeg = ct00; cend = ct00 + seg1; }
        else         { if (seg2 <= 0) break; rb = rb0 + 1; cbeg = 0; cend = seg2; }
        const int R0 = rb * TM;

        // segment prologue: A + P(cbeg) [group 0], P(cbeg+1) [group 1]
        load_tile(sb + SM_A,  g_a16 + (size_t)R0 * DD, tid);
        load_tile(sb + SM_P0, g_p16 + (size_t)cbeg * TN * DD, tid);
        asm volatile("cp.async.commit_group;");
        if (cbeg + 1 < cend)
            load_tile(sb + SM_P1, g_p16 + (size_t)(cbeg + 1) * TN * DD, tid);
        asm volatile("cp.async.commit_group;");

        float sum[2][2], mx[2][2], dg[2][2];
        #pragma unroll
        for (int mf = 0; mf < 2; ++mf)
            #pragma unroll
            for (int h = 0; h < 2; ++h) { sum[mf][h]=0.f; mx[mf][h]=NEGINF; dg[mf][h]=0.f; }

        int grow[2][2];
        #pragma unroll
        for (int mf = 0; mf < 2; ++mf)
            #pragma unroll
            for (int h = 0; h < 2; ++h)
                grow[mf][h] = R0 + warp_m*32 + mf*16 + (lane >> 2) + 8*h;

        #pragma unroll 1
        for (int t = cbeg; t < cend; ++t) {
            const int i = t - cbeg;
            if (t + 1 < cend) asm volatile("cp.async.wait_group 1;");
            else              asm volatile("cp.async.wait_group 0;");
            __syncthreads();

            const uint32_t pb = (i & 1) ? SM_P1 : SM_P0;
            uint32_t bBase[2];
            #pragma unroll
            for (int nfp = 0; nfp < 2; ++nfp)
                bBase[nfp] = sb + pb + (uint32_t)(warp_n*32 + nfp*16 + (int)lrow) * 512u;

            uint32_t acc[2][4][2];
            #pragma unroll
            for (int mf = 0; mf < 2; ++mf)
                #pragma unroll
                for (int nf = 0; nf < 4; ++nf) { acc[mf][nf][0] = 0u; acc[mf][nf][1] = 0u; }

            #pragma unroll
            for (int ks = 0; ks < 16; ++ks) {
                const uint32_t coff = (((uint32_t)(2*ks) + khalf) ^ xorp) << 4;
                uint32_t a[2][4];
                #pragma unroll
                for (int mf = 0; mf < 2; ++mf)
                    LDSM_X4(a[mf][0], a[mf][1], a[mf][2], a[mf][3], aBase[mf] + coff);
                uint32_t b[2][4];
                #pragma unroll
                for (int nfp = 0; nfp < 2; ++nfp)
                    LDSM_X4(b[nfp][0], b[nfp][1], b[nfp][2], b[nfp][3], bBase[nfp] + coff);
                #pragma unroll
                for (int mf = 0; mf < 2; ++mf) {
                    MMA16816H(acc[mf][0], a[mf], b[0][0], b[0][2]);
                    MMA16816H(acc[mf][1], a[mf], b[0][1], b[0][3]);
                    MMA16816H(acc[mf][2], a[mf], b[1][0], b[1][2]);
                    MMA16816H(acc[mf][3], a[mf], b[1][1], b[1][3]);
                }
            }

            __syncthreads();
            if (t + 2 < cend) {
                load_tile(sb + pb, g_p16 + (size_t)(t + 2) * TN * DD, tid);
                asm volatile("cp.async.commit_group;");
            } else {
                asm volatile("cp.async.commit_group;");   // keep group count in step
            }

            // Epilogue: fold 128x128 tile into streaming stats (registers only)
            if (t != rb) {
                #pragma unroll
                for (int mf = 0; mf < 2; ++mf) {
                    #pragma unroll
                    for (int h = 0; h < 2; ++h) {
                        float lsum = 0.f, lmx = mx[mf][h];
                        #pragma unroll
                        for (int nf = 0; nf < 4; ++nf) {
                            float2 vv = __half22float2(*(__half2*)&acc[mf][nf][h]);
                            float ex0, ex1;
                            asm("ex2.approx.f32 %0, %1;" : "=f"(ex0) : "f"(fmaf(vv.x, C1F, -C1F)));
                            asm("ex2.approx.f32 %0, %1;" : "=f"(ex1) : "f"(fmaf(vv.y, C1F, -C1F)));
                            lsum += ex0 + ex1;
                            lmx = fmaxf(lmx, fmaxf(vv.x, vv.y));
                        }
                        sum[mf][h] += lsum;
                        mx[mf][h] = lmx;
                    }
                }
            } else {
                const int cb0 = t*TN + warp_n*32 + (lane & 3)*2;
                #pragma unroll
                for (int mf = 0; mf < 2; ++mf) {
                    #pragma unroll
                    for (int h = 0; h < 2; ++h) {
                        const int r = grow[mf][h];
                        float lsum = 0.f;
                        #pragma unroll
                        for (int nf = 0; nf < 4; ++nf) {
                            float2 vv = __half22float2(*(__half2*)&acc[mf][nf][h]);
                            float ex0, ex1;
                            asm("ex2.approx.f32 %0, %1;" : "=f"(ex0) : "f"(fmaf(vv.x, C1F, -C1F)));
                            asm("ex2.approx.f32 %0, %1;" : "=f"(ex1) : "f"(fmaf(vv.y, C1F, -C1F)));
                            lsum += ex0 + ex1;
                            bool d0 = ((cb0 + nf*8    ) == r);
                            bool d1 = ((cb0 + nf*8 + 1) == r);
                            mx[mf][h] = fmaxf(mx[mf][h], d0 ? NEGINF : vv.x);
                            mx[mf][h] = fmaxf(mx[mf][h], d1 ? NEGINF : vv.y);
                            if (d0) dg[mf][h] = vv.x;
                            if (d1) dg[mf][h] = vv.y;
                        }
                        sum[mf][h] += lsum;
                    }
                }
            }
        }

        // Quad reduction (lanes 4q..4q+3 share rows)
        #pragma unroll
        for (int mf = 0; mf < 2; ++mf) {
            #pragma unroll
            for (int h = 0; h < 2; ++h) {
                #pragma unroll
                for (int o = 1; o < 4; o <<= 1) {
                    sum[mf][h] += __shfl_xor_sync(0xffffffffu, sum[mf][h], o);
                    mx[mf][h]  = fmaxf(mx[mf][h], __shfl_xor_sync(0xffffffffu, mx[mf][h], o));
                    dg[mf][h]  += __shfl_xor_sync(0xffffffffu, dg[mf][h], o);
                }
            }
        }

        // Cross-warp_n combine via smem stats region, then atomic flush
        if ((lane & 3) == 0) {
            #pragma unroll
            for (int mf = 0; mf < 2; ++mf) {
                #pragma unroll
                for (int h = 0; h < 2; ++h) {
                    int rl = warp_m*32 + mf*16 + (lane >> 2) + 8*h;
                    sSum[warp_n*128 + rl] = sum[mf][h];
                    sMax[warp_n*128 + rl] = mx[mf][h];
                    sDg [warp_n*128 + rl] = dg[mf][h];
                }
            }
        }
        __syncthreads();
        if (tid < 128) {
            float S = 0.f, M = NEGINF, D = 0.f;
            #pragma unroll
            for (int w = 0; w < 4; ++w) {
                S += sSum[w*128 + tid];
                M = fmaxf(M, sMax[w*128 + tid]);
                D += sDg[w*128 + tid];
            }
            atomicAdd(&g_psum[R0 + tid], S);
            atomicMax(&g_pmaxu[R0 + tid], fmap(M));
            if (cbeg <= rb && rb < cend) g_diag[R0 + tid] = D;
        }
        __syncthreads();   // stats smem + P buffers free for next segment
    }
}

__global__ void finalize_kernel(float* out) {
    __shared__ double sm[256];
    double sloc = 0.0;
    for (int i = threadIdx.x; i < BB; i += 256) {
        float sum = g_psum[i];
        float m = funmap(g_pmaxu[i]);
        float total = sum + __expf((m - 1.0f) * INVT);
        sloc += (double)(INVT * (1.0f - g_diag[i]) + logf(total));
    }
    sm[threadIdx.x] = sloc;
    __syncthreads();
    for (int st = 128; st > 0; st >>= 1) {
        if (threadIdx.x < st) sm[threadIdx.x] += sm[threadIdx.x + st];
        __syncthreads();
    }
    if (threadIdx.x == 0) out[0] = (float)(sm[0] / (double)BB);
}

extern "C" void kernel_launch(void* const* d_in, const int* in_sizes, int n_in,
                              void* d_out, int out_size) {
    const float* anchor   = (const float*)d_in[0];
    const float* positive = (const float*)d_in[1];
    cudaFuncSetAttribute(fused_kernel, cudaFuncAttributeMaxDynamicSharedMemorySize, SMEM_BYTES);
    nrm_kernel<<<dim3(BB/16, 2), 512>>>(anchor, positive);
    fused_kernel<<<NCTA, 512, SMEM_BYTES>>>();
    finalize_kernel<<<1, 256>>>((float*)d_out);
}